// round 13
// baseline (speedup 1.0000x reference)
#include <cuda_runtime.h>
#include <mma.h>
#include <cstdint>
#include <math.h>

using namespace nvcuda;

#define BATCH 2
#define SEQ   2048
#define EMB   1024
#define NHEAD 16
#define HDIM  64
#define E3    3072

// Scratch (__device__ globals per allocation rules)
__device__ float g_qkv  [(size_t)BATCH * SEQ * E3];            // 50 MB
__device__ float g_ctx  [(size_t)BATCH * SEQ * EMB];           // 16 MB
__device__ float g_ctx0 [(size_t)BATCH * SEQ * EMB];           // 16 MB partial
__device__ float g_ctx1 [(size_t)BATCH * SEQ * EMB];           // 16 MB partial
__device__ float g_attn [(size_t)BATCH * NHEAD * SEQ * SEQ];   // 512 MB fallback

typedef wmma::fragment<wmma::matrix_a, 16, 16, 8, wmma::precision::tf32, wmma::row_major> FragA;
typedef wmma::fragment<wmma::matrix_b, 16, 16, 8, wmma::precision::tf32, wmma::row_major> FragBR;
typedef wmma::fragment<wmma::matrix_b, 16, 16, 8, wmma::precision::tf32, wmma::col_major> FragBC;
typedef wmma::fragment<wmma::accumulator, 16, 16, 8, float> FragC;

template<class F>
__device__ __forceinline__ void to_tf32(F& f) {
    #pragma unroll
    for (int i = 0; i < f.num_elements; i++) f.x[i] = wmma::__float_to_tf32(f.x[i]);
}

__device__ __forceinline__ void cpa16(float* s, const float* g) {
    uint32_t sa = (uint32_t)__cvta_generic_to_shared(s);
    asm volatile("cp.async.ca.shared.global [%0], [%1], 16;" :: "r"(sa), "l"(g));
}
#define CP_COMMIT() asm volatile("cp.async.commit_group;" ::: "memory")
#define CP_WAIT(n)  asm volatile("cp.async.wait_group %0;" :: "n"(n) : "memory")

// ---------------------------------------------------------------------------
// GEMM + bias: C[M,N] = A[M,K] @ B[K,N] + bias[N]
// BM=128, BN=128, BK=32, 256 threads, 2-stage cp.async, 2 CTAs/SM. (R8)
// ---------------------------------------------------------------------------
#define AS_STRIDE 36
#define BS_STRIDE 132
#define AS_BUF (128 * AS_STRIDE)
#define BS_BUF (32 * BS_STRIDE)
#define GSM ((2 * AS_BUF + 2 * BS_BUF) * 4)   // 70656 B

__device__ __forceinline__ void load_gemm_A(float* dst, const float* Ab,
                                            int lda, int tid) {
    const int ar = tid >> 1, ac = (tid & 1) * 16;
    const float* gp = Ab + (size_t)ar * lda + ac;
    float* sp = dst + ar * AS_STRIDE + ac;
    cpa16(sp + 0,  gp + 0);
    cpa16(sp + 4,  gp + 4);
    cpa16(sp + 8,  gp + 8);
    cpa16(sp + 12, gp + 12);
}
__device__ __forceinline__ void load_gemm_B(float* dst, const float* Bb,
                                            int ldb, int tid) {
    #pragma unroll
    for (int t = 0; t < 4; t++) {
        int idx = tid + t * 256;
        int r = idx >> 5, c = (idx & 31) * 4;
        cpa16(&dst[r * BS_STRIDE + c], &Bb[(size_t)r * ldb + c]);
    }
}

__global__ __launch_bounds__(256, 2) void gemm_bias_w(
    const float* __restrict__ A, const float* __restrict__ B,
    const float* __restrict__ bias, float* __restrict__ C, int K, int N)
{
    extern __shared__ float sm[];
    float* As = sm;
    float* Bs = sm + 2 * AS_BUF;
    float* Cs = sm;   // reused after mainloop

    const int m0 = blockIdx.y * 128, n0 = blockIdx.x * 128;
    const int tid = threadIdx.x;
    const int w = tid >> 5;
    const int wr = w >> 1, wc = w & 1;

    FragC acc[2][4];
    #pragma unroll
    for (int i = 0; i < 2; i++)
        #pragma unroll
        for (int j = 0; j < 4; j++) wmma::fill_fragment(acc[i][j], 0.f);

    const int nk = K / 32;
    load_gemm_A(As, A + (size_t)m0 * K, K, tid);
    load_gemm_B(Bs, B + n0, N, tid);
    CP_COMMIT();

    for (int kt = 0; kt < nk; kt++) {
        const int cur = kt & 1;
        if (kt + 1 < nk) {
            const int k0 = (kt + 1) * 32;
            load_gemm_A(As + (cur ^ 1) * AS_BUF, A + (size_t)m0 * K + k0, K, tid);
            load_gemm_B(Bs + (cur ^ 1) * BS_BUF, B + (size_t)k0 * N + n0, N, tid);
            CP_COMMIT();
            CP_WAIT(1);
        } else {
            CP_WAIT(0);
        }
        __syncthreads();

        const float* Ac = As + cur * AS_BUF;
        const float* Bc = Bs + cur * BS_BUF;
        #pragma unroll
        for (int kk = 0; kk < 32; kk += 8) {
            FragA a[2];
            FragBR b[4];
            #pragma unroll
            for (int i = 0; i < 2; i++) {
                wmma::load_matrix_sync(a[i], &Ac[(wr * 32 + i * 16) * AS_STRIDE + kk], AS_STRIDE);
                to_tf32(a[i]);
            }
            #pragma unroll
            for (int j = 0; j < 4; j++) {
                wmma::load_matrix_sync(b[j], &Bc[kk * BS_STRIDE + wc * 64 + j * 16], BS_STRIDE);
                to_tf32(b[j]);
            }
            #pragma unroll
            for (int i = 0; i < 2; i++)
                #pragma unroll
                for (int j = 0; j < 4; j++)
                    wmma::mma_sync(acc[i][j], a[i], b[j], acc[i][j]);
        }
        __syncthreads();
    }

    #pragma unroll
    for (int i = 0; i < 2; i++)
        #pragma unroll
        for (int j = 0; j < 4; j++)
            wmma::store_matrix_sync(&Cs[(wr * 32 + i * 16) * BS_STRIDE + wc * 64 + j * 16],
                                    acc[i][j], BS_STRIDE, wmma::mem_row_major);
    __syncthreads();
    #pragma unroll
    for (int t = 0; t < 16; t++) {
        int idx = tid + t * 256;
        int r = idx >> 5, c = (idx & 31) * 4;
        float4 v = *(float4*)&Cs[r * BS_STRIDE + c];
        const float* bp = bias + n0 + c;
        v.x += bp[0]; v.y += bp[1]; v.z += bp[2]; v.w += bp[3];
        *(float4*)&C[(size_t)(m0 + r) * N + n0 + c] = v;
    }
}

// ---------------------------------------------------------------------------
// Scores: attn[bh,i,j] = Q_i . K_j  (RAW — scale/ALiBi applied in softmax)
// grid(16,16,32). Fragments stored directly to global, no epilogue staging.
// ---------------------------------------------------------------------------
#define QK_STRIDE 68
#define SSM (2 * 128 * QK_STRIDE * 4)   // 69632 B

__global__ __launch_bounds__(256, 2) void scores_w(
    const float* __restrict__ qkv, float* __restrict__ attn)
{
    extern __shared__ float sm[];
    float* Qs = sm;                      // [128][68]
    float* Ks = sm + 128 * QK_STRIDE;    // [128][68]

    const int bh = blockIdx.z, b = bh >> 4, h = bh & 15;
    const int i0 = blockIdx.y * 128, j0 = blockIdx.x * 128;
    const float* Qg = qkv + (size_t)b * SEQ * E3 + h * 192;
    const float* Kg = qkv + (size_t)b * SEQ * E3 + h * 192 + 64;

    const int tid = threadIdx.x;
    const int w = tid >> 5;
    const int wr = w >> 1, wc = w & 1;

    #pragma unroll
    for (int t = 0; t < 8; t++) {
        int idx = tid + t * 256;
        int r = idx >> 4, c = (idx & 15) * 4;
        cpa16(&Qs[r * QK_STRIDE + c], &Qg[(size_t)(i0 + r) * E3 + c]);
        cpa16(&Ks[r * QK_STRIDE + c], &Kg[(size_t)(j0 + r) * E3 + c]);
    }
    CP_COMMIT();
    CP_WAIT(0);
    __syncthreads();

    FragC acc[2][4];
    #pragma unroll
    for (int i = 0; i < 2; i++)
        #pragma unroll
        for (int j = 0; j < 4; j++) wmma::fill_fragment(acc[i][j], 0.f);

    #pragma unroll
    for (int kk = 0; kk < 64; kk += 8) {
        FragA a[2];
        FragBC bf[4];
        #pragma unroll
        for (int i = 0; i < 2; i++) {
            wmma::load_matrix_sync(a[i], &Qs[(wr * 32 + i * 16) * QK_STRIDE + kk], QK_STRIDE);
            to_tf32(a[i]);
        }
        #pragma unroll
        for (int j = 0; j < 4; j++) {
            wmma::load_matrix_sync(bf[j], &Ks[(wc * 64 + j * 16) * QK_STRIDE + kk], QK_STRIDE);
            to_tf32(bf[j]);
        }
        #pragma unroll
        for (int i = 0; i < 2; i++)
            #pragma unroll
            for (int j = 0; j < 4; j++)
                wmma::mma_sync(acc[i][j], a[i], bf[j], acc[i][j]);
    }

    // Direct fragment stores to global (raw scores)
    float* Abase = attn + ((size_t)bh * SEQ + i0) * SEQ + j0;
    #pragma unroll
    for (int i = 0; i < 2; i++)
        #pragma unroll
        for (int j = 0; j < 4; j++)
            wmma::store_matrix_sync(
                &Abase[(size_t)(wr * 32 + i * 16) * SEQ + wc * 64 + j * 16],
                acc[i][j], SEQ, wmma::mem_row_major);
}

// ---------------------------------------------------------------------------
// Softmax, warp-per-row: whole row (2048 f32 = 16 float4/lane) in registers,
// shuffle-only reductions, no barriers, streaming cache hints.
// Fused scale + ALiBi. grid = rows/8, 256 threads.
// ---------------------------------------------------------------------------
__global__ __launch_bounds__(256) void softmax_kernel(float* __restrict__ attn)
{
    const int wid  = threadIdx.x >> 5;
    const int lane = threadIdx.x & 31;
    const int row  = blockIdx.x * 8 + wid;          // bh*2048 + i
    const int i = row & (SEQ - 1);
    const int h = (row >> 11) & (NHEAD - 1);
    const float slope = exp2f(-0.5f * (float)(h + 1));

    float4* p4 = (float4*)(attn + (size_t)row * SEQ);

    float4 v[16];
    #pragma unroll
    for (int t = 0; t < 16; t++) v[t] = __ldcs(&p4[t * 32 + lane]);

    // scale + ALiBi, tracking local max
    float m = -INFINITY;
    #pragma unroll
    for (int t = 0; t < 16; t++) {
        const float base = slope * (float)((t * 32 + lane) * 4 - i);
        v[t].x = v[t].x * 0.125f + base;
        v[t].y = v[t].y * 0.125f + base + slope;
        v[t].z = v[t].z * 0.125f + base + 2.f * slope;
        v[t].w = v[t].w * 0.125f + base + 3.f * slope;
        m = fmaxf(m, fmaxf(fmaxf(v[t].x, v[t].y), fmaxf(v[t].z, v[t].w)));
    }
    #pragma unroll
    for (int o = 16; o > 0; o >>= 1)
        m = fmaxf(m, __shfl_xor_sync(0xffffffffu, m, o));

    float s = 0.f;
    #pragma unroll
    for (int t = 0; t < 16; t++) {
        v[t].x = __expf(v[t].x - m);
        v[t].y = __expf(v[t].y - m);
        v[t].z = __expf(v[t].z - m);
        v[t].w = __expf(v[t].w - m);
        s += v[t].x + v[t].y + v[t].z + v[t].w;
    }
    #pragma unroll
    for (int o = 16; o > 0; o >>= 1)
        s += __shfl_xor_sync(0xffffffffu, s, o);

    const float inv = 1.0f / s;
    #pragma unroll
    for (int t = 0; t < 16; t++) {
        v[t].x *= inv; v[t].y *= inv; v[t].z *= inv; v[t].w *= inv;
        __stcs(&p4[t * 32 + lane], v[t]);
    }
}

// ---------------------------------------------------------------------------
// AV split-K x2 (R8): grid(16, 2, 32). BM=128, BN=64, BK=32, 2-stage.
// ---------------------------------------------------------------------------
#define AVA_BUF (128 * 36)
#define AVV_BUF (32 * 68)
#define AVSM ((2 * AVA_BUF + 2 * AVV_BUF) * 4)   // 54272 B

__device__ __forceinline__ void load_av_A(float* dst, const float* Ab, int tid) {
    const int ar = tid >> 1, ac = (tid & 1) * 16;
    const float* gp = Ab + (size_t)ar * SEQ + ac;
    float* sp = dst + ar * 36 + ac;
    cpa16(sp + 0,  gp + 0);
    cpa16(sp + 4,  gp + 4);
    cpa16(sp + 8,  gp + 8);
    cpa16(sp + 12, gp + 12);
}
__device__ __forceinline__ void load_av_V(float* dst, const float* Vb, int tid) {
    const int vr = tid >> 4, vc = (tid & 15) * 4;
    cpa16(&dst[vr * 68 + vc],        &Vb[(size_t)vr * E3 + vc]);
    cpa16(&dst[(vr + 16) * 68 + vc], &Vb[(size_t)(vr + 16) * E3 + vc]);
}

__global__ __launch_bounds__(256) void av_w(
    const float* __restrict__ attn, const float* __restrict__ qkv,
    float* __restrict__ ctx0, float* __restrict__ ctx1)
{
    extern __shared__ float sm[];
    float* As = sm;                    // 2 x [128][36]
    float* Vs = sm + 2 * AVA_BUF;      // 2 x [32][68]

    const int bh = blockIdx.z, b = bh >> 4, h = bh & 15;
    const int i0 = blockIdx.x * 128;
    const int half = blockIdx.y;
    const int kbase = half * (SEQ / 2);
    float* ctx = half ? ctx1 : ctx0;

    const float* Ag = attn + ((size_t)bh * SEQ + i0) * SEQ + kbase;
    const float* Vg = qkv + (size_t)b * SEQ * E3 + (size_t)kbase * E3 + h * 192 + 128;

    const int tid = threadIdx.x;
    const int w = tid >> 5;
    const int wr = w >> 1, wc = w & 1;

    FragC acc[2][2];
    #pragma unroll
    for (int i = 0; i < 2; i++)
        #pragma unroll
        for (int j = 0; j < 2; j++) wmma::fill_fragment(acc[i][j], 0.f);

    load_av_A(As, Ag, tid);
    load_av_V(Vs, Vg, tid);
    CP_COMMIT();

    const int nk = (SEQ / 2) / 32;  // 32
    for (int kt = 0; kt < nk; kt++) {
        const int cur = kt & 1;
        if (kt + 1 < nk) {
            const int k0 = (kt + 1) * 32;
            load_av_A(As + (cur ^ 1) * AVA_BUF, Ag + k0, tid);
            load_av_V(Vs + (cur ^ 1) * AVV_BUF, Vg + (size_t)k0 * E3, tid);
            CP_COMMIT();
            CP_WAIT(1);
        } else {
            CP_WAIT(0);
        }
        __syncthreads();

        const float* Ac = As + cur * AVA_BUF;
        const float* Vc = Vs + cur * AVV_BUF;
        #pragma unroll
        for (int kk = 0; kk < 32; kk += 8) {
            FragA a[2];
            FragBR bf[2];
            #pragma unroll
            for (int i = 0; i < 2; i++) {
                wmma::load_matrix_sync(a[i], &Ac[(wr * 32 + i * 16) * 36 + kk], 36);
                to_tf32(a[i]);
            }
            #pragma unroll
            for (int j = 0; j < 2; j++) {
                wmma::load_matrix_sync(bf[j], &Vc[kk * 68 + wc * 32 + j * 16], 68);
                to_tf32(bf[j]);
            }
            #pragma unroll
            for (int i = 0; i < 2; i++)
                #pragma unroll
                for (int j = 0; j < 2; j++)
                    wmma::mma_sync(acc[i][j], a[i], bf[j], acc[i][j]);
        }
        __syncthreads();
    }

    #pragma unroll
    for (int i = 0; i < 2; i++) {
        const int q = i0 + wr * 32 + i * 16;
        #pragma unroll
        for (int j = 0; j < 2; j++)
            wmma::store_matrix_sync(
                &ctx[((size_t)(b * SEQ + q)) * EMB + h * HDIM + wc * 32 + j * 16],
                acc[i][j], EMB, wmma::mem_row_major);
    }
}

// ---------------------------------------------------------------------------
// Combine split-K partials: ctx = ctx0 + ctx1 (float4)
// ---------------------------------------------------------------------------
__global__ __launch_bounds__(256) void combine_ctx(
    const float* __restrict__ c0, const float* __restrict__ c1,
    float* __restrict__ ctx)
{
    const size_t i = ((size_t)blockIdx.x * 256 + threadIdx.x) * 4;
    float4 a = *(const float4*)(c0 + i);
    float4 b = *(const float4*)(c1 + i);
    a.x += b.x; a.y += b.y; a.z += b.z; a.w += b.w;
    *(float4*)(ctx + i) = a;
}

// ---------------------------------------------------------------------------
extern "C" void kernel_launch(void* const* d_in, const int* in_sizes, int n_in,
                              void* d_out, int out_size)
{
    const float* x    = (const float*)d_in[0];
    const float* Wqkv = (const float*)d_in[1];
    const float* bqkv = (const float*)d_in[2];
    const float* Wout = (const float*)d_in[3];
    const float* bout = (const float*)d_in[4];
    float* out = (float*)d_out;

    const long long OUT_ELEMS  = (long long)BATCH * SEQ * EMB;
    const long long ATTN_ELEMS = (long long)BATCH * NHEAD * SEQ * SEQ;

    float *qkv, *ctx, *ctx0, *ctx1, *attn;
    cudaGetSymbolAddress((void**)&qkv,  g_qkv);
    cudaGetSymbolAddress((void**)&ctx,  g_ctx);
    cudaGetSymbolAddress((void**)&ctx0, g_ctx0);
    cudaGetSymbolAddress((void**)&ctx1, g_ctx1);
    if ((long long)out_size >= OUT_ELEMS + ATTN_ELEMS) {
        attn = out + OUT_ELEMS;
    } else {
        cudaGetSymbolAddress((void**)&attn, g_attn);
    }

    cudaFuncSetAttribute(gemm_bias_w, cudaFuncAttributeMaxDynamicSharedMemorySize, GSM);
    cudaFuncSetAttribute(scores_w,    cudaFuncAttributeMaxDynamicSharedMemorySize, SSM);
    cudaFuncSetAttribute(av_w,        cudaFuncAttributeMaxDynamicSharedMemorySize, AVSM);

    const int M = BATCH * SEQ;  // 4096

    // 1) QKV projection
    gemm_bias_w<<<dim3(E3 / 128, M / 128), 256, GSM>>>(x, Wqkv, bqkv, qkv, EMB, E3);

    // 2) Raw scores (QK^T)
    scores_w<<<dim3(SEQ / 128, SEQ / 128, BATCH * NHEAD), 256, SSM>>>(qkv, attn);

    // 3) Softmax (warp-per-row) with fused scale + ALiBi
    softmax_kernel<<<(BATCH * NHEAD * SEQ) / 8, 256>>>(attn);

    // 4) AV (split-K x2) + combine
    av_w<<<dim3(SEQ / 128, 2, BATCH * NHEAD), 256, AVSM>>>(attn, qkv, ctx0, ctx1);
    combine_ctx<<<(int)(OUT_ELEMS / 4 / 256), 256>>>(ctx0, ctx1, ctx);

    // 5) Output projection
    gemm_bias_w<<<dim3(EMB / 128, M / 128), 256, GSM>>>(ctx, Wout, bout, out, EMB, EMB);
}

// round 15
// speedup vs baseline: 2.2676x; 2.2676x over previous
#include <cuda_runtime.h>
#include <cuda_fp16.h>
#include <mma.h>
#include <cstdint>
#include <math.h>

using namespace nvcuda;

#define BATCH 2
#define SEQ   2048
#define EMB   1024
#define NHEAD 16
#define HDIM  64
#define E3    3072

// Scratch (__device__ globals per allocation rules)
__device__ __half g_xh   [(size_t)BATCH * SEQ * EMB];            //  8 MB
__device__ __half g_wqkvh[(size_t)EMB * E3];                     //  6 MB
__device__ __half g_wouth[(size_t)EMB * EMB];                    //  2 MB
__device__ __half g_qkvh [(size_t)BATCH * SEQ * E3];             // 25 MB
__device__ __half g_attnh[(size_t)BATCH * NHEAD * SEQ * SEQ];    // 256 MB fp16 probs
__device__ __half g_ctxh [(size_t)BATCH * SEQ * EMB];            //  8 MB
__device__ float  g_ctx0 [(size_t)BATCH * SEQ * EMB];            // 16 MB partial
__device__ float  g_ctx1 [(size_t)BATCH * SEQ * EMB];            // 16 MB partial
__device__ float  g_attn [(size_t)BATCH * NHEAD * SEQ * SEQ];    // 512 MB fallback

typedef wmma::fragment<wmma::matrix_a, 16, 16, 16, half, wmma::row_major> HFragA;
typedef wmma::fragment<wmma::matrix_b, 16, 16, 16, half, wmma::row_major> HFragBR;
typedef wmma::fragment<wmma::matrix_b, 16, 16, 16, half, wmma::col_major> HFragBC;
typedef wmma::fragment<wmma::accumulator, 16, 16, 16, float> HFragC;

__device__ __forceinline__ void cpa16(void* s, const void* g) {
    uint32_t sa = (uint32_t)__cvta_generic_to_shared(s);
    asm volatile("cp.async.ca.shared.global [%0], [%1], 16;" :: "r"(sa), "l"(g));
}
#define CP_COMMIT() asm volatile("cp.async.commit_group;" ::: "memory")
#define CP_WAIT(n)  asm volatile("cp.async.wait_group %0;" :: "n"(n) : "memory")

// ---------------------------------------------------------------------------
// f32 -> f16 conversion, 8 elems/thread
// ---------------------------------------------------------------------------
__global__ __launch_bounds__(256) void f2h_kernel(
    const float* __restrict__ in, __half* __restrict__ out)
{
    const size_t i = ((size_t)blockIdx.x * 256 + threadIdx.x) * 8;
    float4 a = *(const float4*)(in + i);
    float4 b = *(const float4*)(in + i + 4);
    __half2 h[4];
    h[0] = __floats2half2_rn(a.x, a.y);
    h[1] = __floats2half2_rn(a.z, a.w);
    h[2] = __floats2half2_rn(b.x, b.y);
    h[3] = __floats2half2_rn(b.z, b.w);
    *(uint4*)(out + i) = *(uint4*)h;
}

// ---------------------------------------------------------------------------
// GEMM + bias (fp16 operands, fp32 accum): C[M,N] = A[M,K] @ B[K,N] + bias
// BM=128, BN=128, BK=32, 256 threads, 2-stage cp.async, 2 CTAs/SM.
// OutT = __half (qkv) or float (final out).
// ---------------------------------------------------------------------------
#define AS_H 40
#define BS_H 136
#define AS_BUF_H (128 * AS_H)   // halfs
#define BS_BUF_H (32 * BS_H)
#define GSM 67584               // f32 C staging [128][132] dominates

__device__ __forceinline__ void load_gA_h(__half* dst, const __half* Ab,
                                          int lda, int tid) {
    const int ar = tid >> 1, ac = (tid & 1) * 16;
    const __half* gp = Ab + (size_t)ar * lda + ac;
    __half* sp = dst + ar * AS_H + ac;
    cpa16(sp,     gp);
    cpa16(sp + 8, gp + 8);
}
__device__ __forceinline__ void load_gB_h(__half* dst, const __half* Bb,
                                          int ldb, int tid) {
    #pragma unroll
    for (int t = 0; t < 2; t++) {
        int idx = tid + t * 256;
        int r = idx >> 4, c = (idx & 15) * 8;
        cpa16(&dst[r * BS_H + c], &Bb[(size_t)r * ldb + c]);
    }
}

template<typename OutT>
__global__ __launch_bounds__(256, 2) void gemm_bias_h(
    const __half* __restrict__ A, const __half* __restrict__ B,
    const float* __restrict__ bias, OutT* __restrict__ C, int K, int N)
{
    extern __shared__ char smemraw[];
    __half* As = (__half*)smemraw;
    __half* Bs = As + 2 * AS_BUF_H;
    float*  Cs = (float*)smemraw;   // reused after mainloop

    const int m0 = blockIdx.y * 128, n0 = blockIdx.x * 128;
    const int tid = threadIdx.x;
    const int w = tid >> 5;
    const int wr = w >> 1, wc = w & 1;

    HFragC acc[2][4];
    #pragma unroll
    for (int i = 0; i < 2; i++)
        #pragma unroll
        for (int j = 0; j < 4; j++) wmma::fill_fragment(acc[i][j], 0.f);

    const int nk = K / 32;
    load_gA_h(As, A + (size_t)m0 * K, K, tid);
    load_gB_h(Bs, B + n0, N, tid);
    CP_COMMIT();

    for (int kt = 0; kt < nk; kt++) {
        const int cur = kt & 1;
        if (kt + 1 < nk) {
            const int k0 = (kt + 1) * 32;
            load_gA_h(As + (cur ^ 1) * AS_BUF_H, A + (size_t)m0 * K + k0, K, tid);
            load_gB_h(Bs + (cur ^ 1) * BS_BUF_H, B + (size_t)k0 * N + n0, N, tid);
            CP_COMMIT();
            CP_WAIT(1);
        } else {
            CP_WAIT(0);
        }
        __syncthreads();

        const __half* Ac = As + cur * AS_BUF_H;
        const __half* Bc = Bs + cur * BS_BUF_H;
        #pragma unroll
        for (int kk = 0; kk < 32; kk += 16) {
            HFragA a[2];
            HFragBR b[4];
            #pragma unroll
            for (int i = 0; i < 2; i++)
                wmma::load_matrix_sync(a[i], &Ac[(wr * 32 + i * 16) * AS_H + kk], AS_H);
            #pragma unroll
            for (int j = 0; j < 4; j++)
                wmma::load_matrix_sync(b[j], &Bc[kk * BS_H + wc * 64 + j * 16], BS_H);
            #pragma unroll
            for (int i = 0; i < 2; i++)
                #pragma unroll
                for (int j = 0; j < 4; j++)
                    wmma::mma_sync(acc[i][j], a[i], b[j], acc[i][j]);
        }
        __syncthreads();
    }

    #pragma unroll
    for (int i = 0; i < 2; i++)
        #pragma unroll
        for (int j = 0; j < 4; j++)
            wmma::store_matrix_sync(&Cs[(wr * 32 + i * 16) * 132 + wc * 64 + j * 16],
                                    acc[i][j], 132, wmma::mem_row_major);
    __syncthreads();
    #pragma unroll
    for (int t = 0; t < 16; t++) {
        int idx = tid + t * 256;
        int r = idx >> 5, c = (idx & 31) * 4;
        float4 v = *(float4*)&Cs[r * 132 + c];
        const float* bp = bias + n0 + c;
        v.x += bp[0]; v.y += bp[1]; v.z += bp[2]; v.w += bp[3];
        if constexpr (sizeof(OutT) == 2) {
            __half2 h[2];
            h[0] = __floats2half2_rn(v.x, v.y);
            h[1] = __floats2half2_rn(v.z, v.w);
            *(uint2*)&C[(size_t)(m0 + r) * N + n0 + c] = *(uint2*)h;
        } else {
            *(float4*)&C[(size_t)(m0 + r) * N + n0 + c] = v;
        }
    }
}

// ---------------------------------------------------------------------------
// Scores: attn[bh,i,j] = Q_i . K_j  (RAW f32 — scale/ALiBi in softmax)
// fp16 Q,K from qkv_h. grid(16,16,32). Direct fragment stores.
// ---------------------------------------------------------------------------
#define QK_H 72
#define SSM (2 * 128 * QK_H * 2)   // 36864 B

__global__ __launch_bounds__(256, 2) void scores_h(
    const __half* __restrict__ qkvh, float* __restrict__ attn)
{
    extern __shared__ char smemraw[];
    __half* Qs = (__half*)smemraw;       // [128][72]
    __half* Ks = Qs + 128 * QK_H;        // [128][72]

    const int bh = blockIdx.z, b = bh >> 4, h = bh & 15;
    const int i0 = blockIdx.y * 128, j0 = blockIdx.x * 128;
    const __half* Qg = qkvh + (size_t)b * SEQ * E3 + h * 192;
    const __half* Kg = qkvh + (size_t)b * SEQ * E3 + h * 192 + 64;

    const int tid = threadIdx.x;
    const int w = tid >> 5;
    const int wr = w >> 1, wc = w & 1;

    #pragma unroll
    for (int t = 0; t < 4; t++) {
        int idx = tid + t * 256;
        int r = idx >> 3, c = (idx & 7) * 8;
        cpa16(&Qs[r * QK_H + c], &Qg[(size_t)(i0 + r) * E3 + c]);
        cpa16(&Ks[r * QK_H + c], &Kg[(size_t)(j0 + r) * E3 + c]);
    }
    CP_COMMIT();
    CP_WAIT(0);
    __syncthreads();

    HFragC acc[2][4];
    #pragma unroll
    for (int i = 0; i < 2; i++)
        #pragma unroll
        for (int j = 0; j < 4; j++) wmma::fill_fragment(acc[i][j], 0.f);

    #pragma unroll
    for (int kk = 0; kk < 64; kk += 16) {
        HFragA a[2];
        HFragBC bf[4];
        #pragma unroll
        for (int i = 0; i < 2; i++)
            wmma::load_matrix_sync(a[i], &Qs[(wr * 32 + i * 16) * QK_H + kk], QK_H);
        #pragma unroll
        for (int j = 0; j < 4; j++)
            wmma::load_matrix_sync(bf[j], &Ks[(wc * 64 + j * 16) * QK_H + kk], QK_H);
        #pragma unroll
        for (int i = 0; i < 2; i++)
            #pragma unroll
            for (int j = 0; j < 4; j++)
                wmma::mma_sync(acc[i][j], a[i], bf[j], acc[i][j]);
    }

    float* Abase = attn + ((size_t)bh * SEQ + i0) * SEQ + j0;
    #pragma unroll
    for (int i = 0; i < 2; i++)
        #pragma unroll
        for (int j = 0; j < 4; j++)
            wmma::store_matrix_sync(
                &Abase[(size_t)(wr * 32 + i * 16) * SEQ + wc * 64 + j * 16],
                acc[i][j], SEQ, wmma::mem_row_major);
}

// ---------------------------------------------------------------------------
// Softmax (warp-per-row, fused scale+ALiBi). Writes f32 probs to attn AND
// fp16 probs to attnh. grid = rows/8, 256 threads.
// ---------------------------------------------------------------------------
__global__ __launch_bounds__(256) void softmax_kernel(
    float* __restrict__ attn, __half* __restrict__ attnh)
{
    const int wid  = threadIdx.x >> 5;
    const int lane = threadIdx.x & 31;
    const int row  = blockIdx.x * 8 + wid;
    const int i = row & (SEQ - 1);
    const int h = (row >> 11) & (NHEAD - 1);
    const float slope = exp2f(-0.5f * (float)(h + 1));

    float4* p4 = (float4*)(attn + (size_t)row * SEQ);
    uint2*  ph = (uint2*)(attnh + (size_t)row * SEQ);

    float4 v[16];
    #pragma unroll
    for (int t = 0; t < 16; t++) v[t] = __ldcs(&p4[t * 32 + lane]);

    float m = -INFINITY;
    #pragma unroll
    for (int t = 0; t < 16; t++) {
        const float base = slope * (float)((t * 32 + lane) * 4 - i);
        v[t].x = v[t].x * 0.125f + base;
        v[t].y = v[t].y * 0.125f + base + slope;
        v[t].z = v[t].z * 0.125f + base + 2.f * slope;
        v[t].w = v[t].w * 0.125f + base + 3.f * slope;
        m = fmaxf(m, fmaxf(fmaxf(v[t].x, v[t].y), fmaxf(v[t].z, v[t].w)));
    }
    #pragma unroll
    for (int o = 16; o > 0; o >>= 1)
        m = fmaxf(m, __shfl_xor_sync(0xffffffffu, m, o));

    float s = 0.f;
    #pragma unroll
    for (int t = 0; t < 16; t++) {
        v[t].x = __expf(v[t].x - m);
        v[t].y = __expf(v[t].y - m);
        v[t].z = __expf(v[t].z - m);
        v[t].w = __expf(v[t].w - m);
        s += v[t].x + v[t].y + v[t].z + v[t].w;
    }
    #pragma unroll
    for (int o = 16; o > 0; o >>= 1)
        s += __shfl_xor_sync(0xffffffffu, s, o);

    const float inv = 1.0f / s;
    #pragma unroll
    for (int t = 0; t < 16; t++) {
        v[t].x *= inv; v[t].y *= inv; v[t].z *= inv; v[t].w *= inv;
        __stcs(&p4[t * 32 + lane], v[t]);
        __half2 h2[2];
        h2[0] = __floats2half2_rn(v[t].x, v[t].y);
        h2[1] = __floats2half2_rn(v[t].z, v[t].w);
        __stcs(&ph[t * 32 + lane], *(uint2*)h2);
    }
}

// ---------------------------------------------------------------------------
// AV split-K x2 (fp16 P, V): grid(16, 2, 32). BM=128, BN=64, BK=32, 2-stage.
// ---------------------------------------------------------------------------
#define AVA_H 40
#define AVV_H 72
#define AVA_BUF_H (128 * AVA_H)   // halfs
#define AVV_BUF_H (32 * AVV_H)
#define AVSM ((2 * AVA_BUF_H + 2 * AVV_BUF_H) * 2)   // 29696 B

__device__ __forceinline__ void load_avA_h(__half* dst, const __half* Ab, int tid) {
    const int ar = tid >> 1, ac = (tid & 1) * 16;
    const __half* gp = Ab + (size_t)ar * SEQ + ac;
    __half* sp = dst + ar * AVA_H + ac;
    cpa16(sp,     gp);
    cpa16(sp + 8, gp + 8);
}
__device__ __forceinline__ void load_avV_h(__half* dst, const __half* Vb, int tid) {
    const int r = tid >> 3, c = (tid & 7) * 8;
    cpa16(&dst[r * AVV_H + c], &Vb[(size_t)r * E3 + c]);
}

__global__ __launch_bounds__(256) void av_h(
    const __half* __restrict__ attnh, const __half* __restrict__ qkvh,
    float* __restrict__ ctx0, float* __restrict__ ctx1)
{
    extern __shared__ char smemraw[];
    __half* As = (__half*)smemraw;         // 2 x [128][40]
    __half* Vs = As + 2 * AVA_BUF_H;       // 2 x [32][72]

    const int bh = blockIdx.z, b = bh >> 4, h = bh & 15;
    const int i0 = blockIdx.x * 128;
    const int half_ = blockIdx.y;
    const int kbase = half_ * (SEQ / 2);
    float* ctx = half_ ? ctx1 : ctx0;

    const __half* Ag = attnh + ((size_t)bh * SEQ + i0) * SEQ + kbase;
    const __half* Vg = qkvh + (size_t)b * SEQ * E3 + (size_t)kbase * E3 + h * 192 + 128;

    const int tid = threadIdx.x;
    const int w = tid >> 5;
    const int wr = w >> 1, wc = w & 1;

    HFragC acc[2][2];
    #pragma unroll
    for (int i = 0; i < 2; i++)
        #pragma unroll
        for (int j = 0; j < 2; j++) wmma::fill_fragment(acc[i][j], 0.f);

    load_avA_h(As, Ag, tid);
    load_avV_h(Vs, Vg, tid);
    CP_COMMIT();

    const int nk = (SEQ / 2) / 32;  // 32
    for (int kt = 0; kt < nk; kt++) {
        const int cur = kt & 1;
        if (kt + 1 < nk) {
            const int k0 = (kt + 1) * 32;
            load_avA_h(As + (cur ^ 1) * AVA_BUF_H, Ag + k0, tid);
            load_avV_h(Vs + (cur ^ 1) * AVV_BUF_H, Vg + (size_t)k0 * E3, tid);
            CP_COMMIT();
            CP_WAIT(1);
        } else {
            CP_WAIT(0);
        }
        __syncthreads();

        const __half* Ac = As + cur * AVA_BUF_H;
        const __half* Vc = Vs + cur * AVV_BUF_H;
        #pragma unroll
        for (int kk = 0; kk < 32; kk += 16) {
            HFragA a[2];
            HFragBR bf[2];
            #pragma unroll
            for (int i = 0; i < 2; i++)
                wmma::load_matrix_sync(a[i], &Ac[(wr * 32 + i * 16) * AVA_H + kk], AVA_H);
            #pragma unroll
            for (int j = 0; j < 2; j++)
                wmma::load_matrix_sync(bf[j], &Vc[kk * AVV_H + wc * 32 + j * 16], AVV_H);
            #pragma unroll
            for (int i = 0; i < 2; i++)
                #pragma unroll
                for (int j = 0; j < 2; j++)
                    wmma::mma_sync(acc[i][j], a[i], bf[j], acc[i][j]);
        }
        __syncthreads();
    }

    #pragma unroll
    for (int i = 0; i < 2; i++) {
        const int q = i0 + wr * 32 + i * 16;
        #pragma unroll
        for (int j = 0; j < 2; j++)
            wmma::store_matrix_sync(
                &ctx[((size_t)(b * SEQ + q)) * EMB + h * HDIM + wc * 32 + j * 16],
                acc[i][j], EMB, wmma::mem_row_major);
    }
}

// ---------------------------------------------------------------------------
// Combine split-K partials -> fp16 ctx: 8 elems/thread
// ---------------------------------------------------------------------------
__global__ __launch_bounds__(256) void combine_ctx(
    const float* __restrict__ c0, const float* __restrict__ c1,
    __half* __restrict__ ctxh)
{
    const size_t i = ((size_t)blockIdx.x * 256 + threadIdx.x) * 8;
    float4 a0 = *(const float4*)(c0 + i);
    float4 a1 = *(const float4*)(c0 + i + 4);
    float4 b0 = *(const float4*)(c1 + i);
    float4 b1 = *(const float4*)(c1 + i + 4);
    __half2 h[4];
    h[0] = __floats2half2_rn(a0.x + b0.x, a0.y + b0.y);
    h[1] = __floats2half2_rn(a0.z + b0.z, a0.w + b0.w);
    h[2] = __floats2half2_rn(a1.x + b1.x, a1.y + b1.y);
    h[3] = __floats2half2_rn(a1.z + b1.z, a1.w + b1.w);
    *(uint4*)(ctxh + i) = *(uint4*)h;
}

// ---------------------------------------------------------------------------
extern "C" void kernel_launch(void* const* d_in, const int* in_sizes, int n_in,
                              void* d_out, int out_size)
{
    const float* x    = (const float*)d_in[0];
    const float* Wqkv = (const float*)d_in[1];
    const float* bqkv = (const float*)d_in[2];
    const float* Wout = (const float*)d_in[3];
    const float* bout = (const float*)d_in[4];
    float* out = (float*)d_out;

    const long long OUT_ELEMS  = (long long)BATCH * SEQ * EMB;
    const long long ATTN_ELEMS = (long long)BATCH * NHEAD * SEQ * SEQ;

    __half *xh, *wqkvh, *wouth, *qkvh, *attnh, *ctxh;
    float *ctx0, *ctx1, *attn;
    cudaGetSymbolAddress((void**)&xh,    g_xh);
    cudaGetSymbolAddress((void**)&wqkvh, g_wqkvh);
    cudaGetSymbolAddress((void**)&wouth, g_wouth);
    cudaGetSymbolAddress((void**)&qkvh,  g_qkvh);
    cudaGetSymbolAddress((void**)&attnh, g_attnh);
    cudaGetSymbolAddress((void**)&ctxh,  g_ctxh);
    cudaGetSymbolAddress((void**)&ctx0,  g_ctx0);
    cudaGetSymbolAddress((void**)&ctx1,  g_ctx1);
    if ((long long)out_size >= OUT_ELEMS + ATTN_ELEMS) {
        attn = out + OUT_ELEMS;
    } else {
        cudaGetSymbolAddress((void**)&attn, g_attn);
    }

    cudaFuncSetAttribute(gemm_bias_h<__half>, cudaFuncAttributeMaxDynamicSharedMemorySize, GSM);
    cudaFuncSetAttribute(gemm_bias_h<float>,  cudaFuncAttributeMaxDynamicSharedMemorySize, GSM);
    cudaFuncSetAttribute(scores_h,            cudaFuncAttributeMaxDynamicSharedMemorySize, SSM);
    cudaFuncSetAttribute(av_h,                cudaFuncAttributeMaxDynamicSharedMemorySize, AVSM);

    const int M = BATCH * SEQ;  // 4096

    // 0) Convert inputs to fp16
    f2h_kernel<<<(int)((size_t)M * EMB / 2048), 256>>>(x, xh);
    f2h_kernel<<<(int)((size_t)EMB * E3 / 2048), 256>>>(Wqkv, wqkvh);
    f2h_kernel<<<(int)((size_t)EMB * EMB / 2048), 256>>>(Wout, wouth);

    // 1) QKV projection (fp16 out)
    gemm_bias_h<__half><<<dim3(E3 / 128, M / 128), 256, GSM>>>(xh, wqkvh, bqkv, qkvh, EMB, E3);

    // 2) Raw scores (QK^T), f32 out
    scores_h<<<dim3(SEQ / 128, SEQ / 128, BATCH * NHEAD), 256, SSM>>>(qkvh, attn);

    // 3) Softmax: f32 probs + fp16 probs
    softmax_kernel<<<(BATCH * NHEAD * SEQ) / 8, 256>>>(attn, attnh);

    // 4) AV (split-K x2, fp16) + combine to fp16 ctx
    av_h<<<dim3(SEQ / 128, 2, BATCH * NHEAD), 256, AVSM>>>(attnh, qkvh, ctx0, ctx1);
    combine_ctx<<<(int)(OUT_ELEMS / 8 / 256), 256>>>(ctx0, ctx1, ctxh);

    // 5) Output projection (f32 out)
    gemm_bias_h<float><<<dim3(EMB / 128, M / 128), 256, GSM>>>(ctxh, wouth, bout, out, EMB, EMB);
}